// round 7
// baseline (speedup 1.0000x reference)
#include <cuda_runtime.h>
#include <math.h>

#define T_ 128
#define B_ 128
#define I_ 256
#define H_ 256
#define G4_ 1024
#define NCTA 128
#define SLOT_STRIDE 32   // 128B between slots (anti false-sharing)

typedef unsigned long long u64;

__device__ float g_preact[(size_t)T_ * B_ * G4_];
__device__ unsigned g_slot[NCTA * SLOT_STRIDE];

// ---------------------------------------------------------------------------
// Phase 1: preact[t] = x[t]@Wi[t] + bi[t] + bh[t].  Grid (8, T), 256 thr.
// 8x8 micro-tile, packed f32x2 FMAs. (measured ~165us, near fp32 issue floor)
// ---------------------------------------------------------------------------
__global__ __launch_bounds__(256) void lstm_phase1(
    const float* __restrict__ x, const float* __restrict__ Wi,
    const float* __restrict__ bi, const float* __restrict__ bh,
    float* __restrict__ preact)
{
    __shared__ float As[2][16][128];
    __shared__ float Bs[2][16][128];

    const int t = blockIdx.y, n0 = blockIdx.x * 128, tid = threadIdx.x;
    const int tx = tid & 15, ty = tid >> 4;
    const float* xA = x + (size_t)t * (B_ * I_);
    const float* WB = Wi + (size_t)t * (I_ * G4_) + n0;
    const int am = tid >> 1, aq = (tid & 1) * 2;
    const int bk = tid >> 4, bn = (tid & 15) * 4;

    u64 acc2[8][4];
#pragma unroll
    for (int i = 0; i < 8; ++i)
#pragma unroll
        for (int j = 0; j < 4; ++j) acc2[i][j] = 0ULL;

    {
        float4 a0 = *(const float4*)(xA + am * I_ + (aq + 0) * 4);
        float4 a1 = *(const float4*)(xA + am * I_ + (aq + 1) * 4);
        As[0][aq * 4 + 0][am] = a0.x; As[0][aq * 4 + 1][am] = a0.y;
        As[0][aq * 4 + 2][am] = a0.z; As[0][aq * 4 + 3][am] = a0.w;
        As[0][aq * 4 + 4][am] = a1.x; As[0][aq * 4 + 5][am] = a1.y;
        As[0][aq * 4 + 6][am] = a1.z; As[0][aq * 4 + 7][am] = a1.w;
        *(float4*)&Bs[0][bk][bn]      = *(const float4*)(WB + (size_t)bk * G4_ + bn);
        *(float4*)&Bs[0][bk][bn + 64] = *(const float4*)(WB + (size_t)bk * G4_ + bn + 64);
    }
    __syncthreads();

    for (int kt = 0; kt < 16; ++kt) {
        const int cur = kt & 1;
        float4 pa0, pa1, pb0, pb1;
        if (kt < 15) {
            const int k0 = (kt + 1) * 16;
            pa0 = *(const float4*)(xA + am * I_ + k0 + (aq + 0) * 4);
            pa1 = *(const float4*)(xA + am * I_ + k0 + (aq + 1) * 4);
            pb0 = *(const float4*)(WB + (size_t)(k0 + bk) * G4_ + bn);
            pb1 = *(const float4*)(WB + (size_t)(k0 + bk) * G4_ + bn + 64);
        }
#pragma unroll
        for (int kk = 0; kk < 16; ++kk) {
            float4 a0 = *(float4*)&As[cur][kk][ty * 4];
            float4 a1 = *(float4*)&As[cur][kk][64 + ty * 4];
            ulonglong2 bp0 = *(ulonglong2*)&Bs[cur][kk][tx * 4];
            ulonglong2 bp1 = *(ulonglong2*)&Bs[cur][kk][64 + tx * 4];
            float av[8] = {a0.x, a0.y, a0.z, a0.w, a1.x, a1.y, a1.z, a1.w};
#pragma unroll
            for (int i = 0; i < 8; ++i) {
                u64 ad;
                asm("mov.b64 %0, {%1, %1};" : "=l"(ad) : "f"(av[i]));
                asm("fma.rn.f32x2 %0, %1, %2, %0;" : "+l"(acc2[i][0]) : "l"(ad), "l"(bp0.x));
                asm("fma.rn.f32x2 %0, %1, %2, %0;" : "+l"(acc2[i][1]) : "l"(ad), "l"(bp0.y));
                asm("fma.rn.f32x2 %0, %1, %2, %0;" : "+l"(acc2[i][2]) : "l"(ad), "l"(bp1.x));
                asm("fma.rn.f32x2 %0, %1, %2, %0;" : "+l"(acc2[i][3]) : "l"(ad), "l"(bp1.y));
            }
        }
        if (kt < 15) {
            const int nb = cur ^ 1;
            As[nb][aq * 4 + 0][am] = pa0.x; As[nb][aq * 4 + 1][am] = pa0.y;
            As[nb][aq * 4 + 2][am] = pa0.z; As[nb][aq * 4 + 3][am] = pa0.w;
            As[nb][aq * 4 + 4][am] = pa1.x; As[nb][aq * 4 + 5][am] = pa1.y;
            As[nb][aq * 4 + 6][am] = pa1.z; As[nb][aq * 4 + 7][am] = pa1.w;
            *(float4*)&Bs[nb][bk][bn]      = pb0;
            *(float4*)&Bs[nb][bk][bn + 64] = pb1;
            __syncthreads();
        }
    }

    const float* bip = bi + (size_t)t * G4_ + n0;
    const float* bhp = bh + (size_t)t * G4_ + n0;
    float* Cp = preact + (size_t)t * (B_ * G4_) + n0;
    float4 i0 = *(const float4*)(bip + tx * 4);
    float4 h0 = *(const float4*)(bhp + tx * 4);
    float4 i1 = *(const float4*)(bip + 64 + tx * 4);
    float4 h1 = *(const float4*)(bhp + 64 + tx * 4);
    float bs[8] = {i0.x + h0.x, i0.y + h0.y, i0.z + h0.z, i0.w + h0.w,
                   i1.x + h1.x, i1.y + h1.y, i1.z + h1.z, i1.w + h1.w};
#pragma unroll
    for (int i = 0; i < 8; ++i) {
        const int m = (i < 4) ? (ty * 4 + i) : (64 + ty * 4 + (i - 4));
        float a[8];
#pragma unroll
        for (int j = 0; j < 4; ++j)
            asm("mov.b64 {%0, %1}, %2;" : "=f"(a[j * 2]), "=f"(a[j * 2 + 1]) : "l"(acc2[i][j]));
        float4 v0 = make_float4(a[0] + bs[0], a[1] + bs[1], a[2] + bs[2], a[3] + bs[3]);
        float4 v1 = make_float4(a[4] + bs[4], a[5] + bs[5], a[6] + bs[6], a[7] + bs[7]);
        *(float4*)(Cp + (size_t)m * G4_ + tx * 4)      = v0;
        *(float4*)(Cp + (size_t)m * G4_ + 64 + tx * 4) = v1;
    }
}

// ---------------------------------------------------------------------------
// Persistent scan: per-ROW-GROUP barrier (32 CTAs), pre-duplicated h in SMEM
// (u64 {h,h}), split-K 4x(K'=64) with 4x4 micro-tile, SMEM k-reduction,
// fused cell update. Visibility: fence+release / acquire+ldcg.
// ---------------------------------------------------------------------------
__device__ __forceinline__ unsigned ld_acq(const unsigned* p) {
    unsigned v;
    asm volatile("ld.acquire.gpu.global.u32 %0, [%1];" : "=r"(v) : "l"(p) : "memory");
    return v;
}
__device__ __forceinline__ void st_rel(unsigned* p, unsigned v) {
    asm volatile("st.release.gpu.global.u32 [%0], %1;" :: "l"(p), "r"(v) : "memory");
}

__global__ __launch_bounds__(256, 1) void lstm_scan(
    const float* __restrict__ h0, const float* __restrict__ c0,
    const float* __restrict__ Wh,   // [T][H][4H]
    const float* __restrict__ pre,  // [T][B][4H]
    float* __restrict__ outputs,    // [T][B][H]
    float* __restrict__ hfin, float* __restrict__ cfin)
{
    extern __shared__ float smem[];
    // Hs2: [256 k][33 u64] duplicated h  (67584 B)
    u64*   Hs2 = (u64*)smem;
    // Ws:  [256 k][32] gathered gate cols (32768 B), after Hs2
    float* Ws  = smem + (256 * 33 * 2);
    // epilogue scratch aliases Hs2 region:
    float* gred = smem;                 // [4][32][36] k-partials
    float* gsm  = smem + 4 * 32 * 36;   // [32][33] gate exchange

    const int tid = threadIdx.x;
    const int bid = blockIdx.x;
    const int cg = bid & 31, rg = bid >> 5;
    const int hc0 = cg * 8, r0 = rg * 32;

    // epilogue/pv mapping
    const int r  = tid >> 3;            // 0..31
    const int c2 = tid & 7;             // 0..7
    const int oc0 = c2 * 4;
    const int g = oc0 >> 3;
    const int nbase = g * 256 + hc0 + (oc0 & 7);

    // GEMM mapping: 4 k-groups x (8 row-groups x 8 col-groups)
    const int kg  = tid >> 6;           // 0..3
    const int wi2 = (tid & 63) >> 3;    // 0..7 -> rows wi2*4..+3
    const int wj2 = tid & 7;            // 0..7 -> cols wj2*4..+3
    const int kbase = kg * 64;

    const unsigned base = g_slot[bid * SLOT_STRIDE];
    float creg = c0[(r0 + r) * H_ + hc0 + c2];

    for (int t = 0; t < T_; ++t) {
        const float* Wt = Wh + (size_t)t * H_ * G4_;
        const float* pt = pre + (size_t)t * B_ * G4_;

        // prefetch Wh[t], pre[t] (h-independent) before the wait
        float4 wv[8];
#pragma unroll
        for (int i = 0; i < 8; ++i) {
            const int s = i * 256 + tid;
            const int k = s >> 3, q = s & 7;
            const int gg = q >> 1, cc = (q & 1) * 4;
            wv[i] = __ldg((const float4*)(Wt + (size_t)k * G4_ + gg * 256 + hc0 + cc));
        }
        float4 pv = __ldg((const float4*)(pt + (size_t)(r0 + r) * G4_ + nbase));
#pragma unroll
        for (int i = 0; i < 8; ++i) {
            const int s = i * 256 + tid;
            const int k = s >> 3, q = s & 7;
            *(float4*)(Ws + k * 32 + q * 4) = wv[i];
        }

        // inter-step barrier: only the 32 CTAs of this row group matter
        if (t > 0) {
            if (tid < 32) {
                const unsigned tgt = base + (unsigned)t;
                const unsigned* sl = &g_slot[(rg * 32 + tid) * SLOT_STRIDE];
                while (ld_acq(sl) < tgt) __nanosleep(32);
            }
        }
        __syncthreads();

        // fill Hs2 with duplicated h[t-1] (L2-coherent reads)
        const float* hp = (t == 0) ? h0 : (outputs + (size_t)(t - 1) * B_ * H_);
#pragma unroll
        for (int a = 0; a < 4; ++a) {
            const int rr = (tid >> 5) + a * 8;
            const float* src = hp + (size_t)(r0 + rr) * H_;
            u64* dst = Hs2 + rr;
#pragma unroll
            for (int b = 0; b < 8; ++b) {
                const int k = (tid & 31) + b * 32;
                const float hv = __ldcg(src + k);
                u64 hd;
                asm("mov.b64 %0, {%1, %1};" : "=l"(hd) : "f"(hv));
                dst[k * 33] = hd;
            }
        }
        __syncthreads();

        // GEMM: 4 rows x 4 cols per thread over K'=64 (no dup-movs in loop)
        u64 acc2[4][2];
#pragma unroll
        for (int e = 0; e < 4; ++e) { acc2[e][0] = 0ULL; acc2[e][1] = 0ULL; }
        {
            const u64*  hq = Hs2 + wi2 * 4;
            const float* wq = Ws + wj2 * 4;
#pragma unroll 4
            for (int k = 0; k < 64; ++k) {
                const int kk = kbase + k;
                const u64 hd0 = hq[kk * 33 + 0];
                const u64 hd1 = hq[kk * 33 + 1];
                const u64 hd2 = hq[kk * 33 + 2];
                const u64 hd3 = hq[kk * 33 + 3];
                ulonglong2 w2 = *(const ulonglong2*)(wq + kk * 32);
                asm("fma.rn.f32x2 %0, %1, %2, %0;" : "+l"(acc2[0][0]) : "l"(hd0), "l"(w2.x));
                asm("fma.rn.f32x2 %0, %1, %2, %0;" : "+l"(acc2[0][1]) : "l"(hd0), "l"(w2.y));
                asm("fma.rn.f32x2 %0, %1, %2, %0;" : "+l"(acc2[1][0]) : "l"(hd1), "l"(w2.x));
                asm("fma.rn.f32x2 %0, %1, %2, %0;" : "+l"(acc2[1][1]) : "l"(hd1), "l"(w2.y));
                asm("fma.rn.f32x2 %0, %1, %2, %0;" : "+l"(acc2[2][0]) : "l"(hd2), "l"(w2.x));
                asm("fma.rn.f32x2 %0, %1, %2, %0;" : "+l"(acc2[2][1]) : "l"(hd2), "l"(w2.y));
                asm("fma.rn.f32x2 %0, %1, %2, %0;" : "+l"(acc2[3][0]) : "l"(hd3), "l"(w2.x));
                asm("fma.rn.f32x2 %0, %1, %2, %0;" : "+l"(acc2[3][1]) : "l"(hd3), "l"(w2.y));
            }
        }
        __syncthreads();  // Hs2 reads done -> gred/gsm (alias) may be written

        // store k-partials
#pragma unroll
        for (int e = 0; e < 4; ++e) {
            float2 p0, p1;
            asm("mov.b64 {%0, %1}, %2;" : "=f"(p0.x), "=f"(p0.y) : "l"(acc2[e][0]));
            asm("mov.b64 {%0, %1}, %2;" : "=f"(p1.x), "=f"(p1.y) : "l"(acc2[e][1]));
            *(float4*)(gred + (size_t)(kg * 32 + wi2 * 4 + e) * 36 + wj2 * 4) =
                make_float4(p0.x, p0.y, p1.x, p1.y);
        }
        __syncthreads();

        // reduce 4 k-partials, add preact, write gate exchange
        {
            float4 s = make_float4(0.f, 0.f, 0.f, 0.f);
#pragma unroll
            for (int q = 0; q < 4; ++q) {
                float4 v = *(const float4*)(gred + (size_t)(q * 32 + r) * 36 + oc0);
                s.x += v.x; s.y += v.y; s.z += v.z; s.w += v.w;
            }
            gsm[r * 33 + oc0 + 0] = s.x + pv.x;
            gsm[r * 33 + oc0 + 1] = s.y + pv.y;
            gsm[r * 33 + oc0 + 2] = s.z + pv.z;
            gsm[r * 33 + oc0 + 3] = s.w + pv.w;
        }
        __syncthreads();

        // fused cell update
        {
            const float iv = gsm[r * 33 +  0 + c2];
            const float fv = gsm[r * 33 +  8 + c2];
            const float ov = gsm[r * 33 + 16 + c2];
            const float gv = gsm[r * 33 + 24 + c2];
            const float ig = 1.f / (1.f + expf(-iv));
            const float fg = 1.f / (1.f + expf(-fv));
            const float og = 1.f / (1.f + expf(-ov));
            const float gt = tanhf(gv);
            creg = fg * creg + ig * gt;
            const float hn = og * tanhf(creg);
            const int row = r0 + r, col = hc0 + c2;
            outputs[(size_t)t * B_ * H_ + row * H_ + col] = hn;
            if (t == T_ - 1) {
                hfin[row * H_ + col] = hn;
                cfin[row * H_ + col] = creg;
            }
        }

        // publish step t
        __threadfence();
        __syncthreads();
        if (tid == 0) st_rel(&g_slot[bid * SLOT_STRIDE], base + (unsigned)(t + 1));
    }
}

extern "C" void kernel_launch(void* const* d_in, const int* in_sizes, int n_in,
                              void* d_out, int out_size)
{
    (void)in_sizes; (void)n_in; (void)out_size;
    const float* x   = (const float*)d_in[0];
    const float* h0  = (const float*)d_in[1];
    const float* c0  = (const float*)d_in[2];
    const float* Wi  = (const float*)d_in[3];
    const float* bi  = (const float*)d_in[4];
    const float* Wh  = (const float*)d_in[5];
    const float* bh  = (const float*)d_in[6];

    float* out     = (float*)d_out;
    float* outputs = out;
    float* hfin    = out + (size_t)T_ * B_ * H_;
    float* cfin    = hfin + (size_t)B_ * H_;

    float* pre;
    cudaGetSymbolAddress((void**)&pre, g_preact);

    // Hs2 (256*33 u64) + Ws (256*32 f32) = 67584 + 32768 = 100352 B
    const int smem_bytes = 256 * 33 * 8 + 256 * 32 * 4;
    cudaFuncSetAttribute(lstm_scan, cudaFuncAttributeMaxDynamicSharedMemorySize,
                         smem_bytes);

    dim3 g1(8, T_);
    lstm_phase1<<<g1, 256>>>(x, Wi, bi, bh, pre);

    lstm_scan<<<NCTA, 256, smem_bytes>>>(h0, c0, Wh, pre, outputs, hfin, cfin);
}

// round 9
// speedup vs baseline: 1.2566x; 1.2566x over previous
#include <cuda_runtime.h>
#include <math.h>

#define T_ 128
#define B_ 128
#define I_ 256
#define H_ 256
#define G4_ 1024
#define NCTA 128

typedef unsigned long long u64;

__device__ float g_preact[(size_t)T_ * B_ * G4_];
__device__ unsigned g_slot[NCTA];

// ---------------------------------------------------------------------------
// Phase 1: preact[t] = x[t]@Wi[t] + bi[t] + bh[t].  Grid (8, T), 256 thr.
// 8x8 micro-tile, packed f32x2 FMAs. (measured ~165us, near fp32 issue floor)
// ---------------------------------------------------------------------------
__global__ __launch_bounds__(256) void lstm_phase1(
    const float* __restrict__ x, const float* __restrict__ Wi,
    const float* __restrict__ bi, const float* __restrict__ bh,
    float* __restrict__ preact)
{
    __shared__ float As[2][16][128];
    __shared__ float Bs[2][16][128];

    const int t = blockIdx.y, n0 = blockIdx.x * 128, tid = threadIdx.x;
    const int tx = tid & 15, ty = tid >> 4;
    const float* xA = x + (size_t)t * (B_ * I_);
    const float* WB = Wi + (size_t)t * (I_ * G4_) + n0;
    const int am = tid >> 1, aq = (tid & 1) * 2;
    const int bk = tid >> 4, bn = (tid & 15) * 4;

    u64 acc2[8][4];
#pragma unroll
    for (int i = 0; i < 8; ++i)
#pragma unroll
        for (int j = 0; j < 4; ++j) acc2[i][j] = 0ULL;

    {
        float4 a0 = *(const float4*)(xA + am * I_ + (aq + 0) * 4);
        float4 a1 = *(const float4*)(xA + am * I_ + (aq + 1) * 4);
        As[0][aq * 4 + 0][am] = a0.x; As[0][aq * 4 + 1][am] = a0.y;
        As[0][aq * 4 + 2][am] = a0.z; As[0][aq * 4 + 3][am] = a0.w;
        As[0][aq * 4 + 4][am] = a1.x; As[0][aq * 4 + 5][am] = a1.y;
        As[0][aq * 4 + 6][am] = a1.z; As[0][aq * 4 + 7][am] = a1.w;
        *(float4*)&Bs[0][bk][bn]      = *(const float4*)(WB + (size_t)bk * G4_ + bn);
        *(float4*)&Bs[0][bk][bn + 64] = *(const float4*)(WB + (size_t)bk * G4_ + bn + 64);
    }
    __syncthreads();

    for (int kt = 0; kt < 16; ++kt) {
        const int cur = kt & 1;
        float4 pa0, pa1, pb0, pb1;
        if (kt < 15) {
            const int k0 = (kt + 1) * 16;
            pa0 = *(const float4*)(xA + am * I_ + k0 + (aq + 0) * 4);
            pa1 = *(const float4*)(xA + am * I_ + k0 + (aq + 1) * 4);
            pb0 = *(const float4*)(WB + (size_t)(k0 + bk) * G4_ + bn);
            pb1 = *(const float4*)(WB + (size_t)(k0 + bk) * G4_ + bn + 64);
        }
#pragma unroll
        for (int kk = 0; kk < 16; ++kk) {
            float4 a0 = *(float4*)&As[cur][kk][ty * 4];
            float4 a1 = *(float4*)&As[cur][kk][64 + ty * 4];
            ulonglong2 bp0 = *(ulonglong2*)&Bs[cur][kk][tx * 4];
            ulonglong2 bp1 = *(ulonglong2*)&Bs[cur][kk][64 + tx * 4];
            float av[8] = {a0.x, a0.y, a0.z, a0.w, a1.x, a1.y, a1.z, a1.w};
#pragma unroll
            for (int i = 0; i < 8; ++i) {
                u64 ad;
                asm("mov.b64 %0, {%1, %1};" : "=l"(ad) : "f"(av[i]));
                asm("fma.rn.f32x2 %0, %1, %2, %0;" : "+l"(acc2[i][0]) : "l"(ad), "l"(bp0.x));
                asm("fma.rn.f32x2 %0, %1, %2, %0;" : "+l"(acc2[i][1]) : "l"(ad), "l"(bp0.y));
                asm("fma.rn.f32x2 %0, %1, %2, %0;" : "+l"(acc2[i][2]) : "l"(ad), "l"(bp1.x));
                asm("fma.rn.f32x2 %0, %1, %2, %0;" : "+l"(acc2[i][3]) : "l"(ad), "l"(bp1.y));
            }
        }
        if (kt < 15) {
            const int nb = cur ^ 1;
            As[nb][aq * 4 + 0][am] = pa0.x; As[nb][aq * 4 + 1][am] = pa0.y;
            As[nb][aq * 4 + 2][am] = pa0.z; As[nb][aq * 4 + 3][am] = pa0.w;
            As[nb][aq * 4 + 4][am] = pa1.x; As[nb][aq * 4 + 5][am] = pa1.y;
            As[nb][aq * 4 + 6][am] = pa1.z; As[nb][aq * 4 + 7][am] = pa1.w;
            *(float4*)&Bs[nb][bk][bn]      = pb0;
            *(float4*)&Bs[nb][bk][bn + 64] = pb1;
            __syncthreads();
        }
    }

    const float* bip = bi + (size_t)t * G4_ + n0;
    const float* bhp = bh + (size_t)t * G4_ + n0;
    float* Cp = preact + (size_t)t * (B_ * G4_) + n0;
    float4 i0 = *(const float4*)(bip + tx * 4);
    float4 h0 = *(const float4*)(bhp + tx * 4);
    float4 i1 = *(const float4*)(bip + 64 + tx * 4);
    float4 h1 = *(const float4*)(bhp + 64 + tx * 4);
    float bs[8] = {i0.x + h0.x, i0.y + h0.y, i0.z + h0.z, i0.w + h0.w,
                   i1.x + h1.x, i1.y + h1.y, i1.z + h1.z, i1.w + h1.w};
#pragma unroll
    for (int i = 0; i < 8; ++i) {
        const int m = (i < 4) ? (ty * 4 + i) : (64 + ty * 4 + (i - 4));
        float a[8];
#pragma unroll
        for (int j = 0; j < 4; ++j)
            asm("mov.b64 {%0, %1}, %2;" : "=f"(a[j * 2]), "=f"(a[j * 2 + 1]) : "l"(acc2[i][j]));
        float4 v0 = make_float4(a[0] + bs[0], a[1] + bs[1], a[2] + bs[2], a[3] + bs[3]);
        float4 v1 = make_float4(a[4] + bs[4], a[5] + bs[5], a[6] + bs[6], a[7] + bs[7]);
        *(float4*)(Cp + (size_t)m * G4_ + tx * 4)      = v0;
        *(float4*)(Cp + (size_t)m * G4_ + 64 + tx * 4) = v1;
    }
}

// ---------------------------------------------------------------------------
// Persistent scan (R5 structure): split-K 4x(K'=64), 4x4 micro-tile, fp32 Hs
// (pad 33). Deltas vs R5: row-group barrier (32 slots, 1 warp polls) and
// non-aliased gred/gsm (drops the post-GEMM syncthreads).
// ---------------------------------------------------------------------------
__device__ __forceinline__ unsigned ld_acq(const unsigned* p) {
    unsigned v;
    asm volatile("ld.acquire.gpu.global.u32 %0, [%1];" : "=r"(v) : "l"(p) : "memory");
    return v;
}
__device__ __forceinline__ void st_rel(unsigned* p, unsigned v) {
    asm volatile("st.release.gpu.global.u32 [%0], %1;" :: "l"(p), "r"(v) : "memory");
}

__global__ __launch_bounds__(256, 1) void lstm_scan(
    const float* __restrict__ h0, const float* __restrict__ c0,
    const float* __restrict__ Wh,   // [T][H][4H]
    const float* __restrict__ pre,  // [T][B][4H]
    float* __restrict__ outputs,    // [T][B][H]
    float* __restrict__ hfin, float* __restrict__ cfin)
{
    extern __shared__ float smem[];
    float* Hs   = smem;                        // [256][33] k-major h tile
    float* Ws   = smem + 256 * 33;             // [256][32] gathered gate cols
    float* gred = smem + 256 * 33 + 256 * 32;  // [4][32][36] k-partials (own region)
    float* gsm  = gred + 4 * 32 * 36;          // [32][33] gate exchange (own region)

    const int tid = threadIdx.x;
    const int bid = blockIdx.x;
    const int cg = bid & 31, rg = bid >> 5;
    const int hc0 = cg * 8, r0 = rg * 32;

    // epilogue/pv mapping
    const int r  = tid >> 3;             // 0..31
    const int c2 = tid & 7;              // 0..7
    const int oc0 = c2 * 4;
    const int g = oc0 >> 3;
    const int nbase = g * 256 + hc0 + (oc0 & 7);

    // GEMM mapping: 4 k-groups x (8 row-groups x 8 col-groups)
    const int kg  = tid >> 6;            // 0..3
    const int wi2 = (tid & 63) >> 3;     // 0..7 -> rows wi2*4..+3
    const int wj2 = tid & 7;             // 0..7 -> cols wj2*4..+3
    const int kbase = kg * 64;

    const unsigned base = g_slot[bid];
    float creg = c0[(r0 + r) * H_ + hc0 + c2];

    for (int t = 0; t < T_; ++t) {
        const float* Wt = Wh + (size_t)t * H_ * G4_;
        const float* pt = pre + (size_t)t * B_ * G4_;

        // prefetch Wh[t], pre[t] (h-independent) before the wait
        float4 wv[8];
#pragma unroll
        for (int i = 0; i < 8; ++i) {
            const int s = i * 256 + tid;
            const int k = s >> 3, q = s & 7;
            const int gg = q >> 1, cc = (q & 1) * 4;
            wv[i] = __ldg((const float4*)(Wt + (size_t)k * G4_ + gg * 256 + hc0 + cc));
        }
        float4 pv = __ldg((const float4*)(pt + (size_t)(r0 + r) * G4_ + nbase));
#pragma unroll
        for (int i = 0; i < 8; ++i) {
            const int s = i * 256 + tid;
            const int k = s >> 3, q = s & 7;
            *(float4*)(Ws + k * 32 + q * 4) = wv[i];
        }

        // inter-step barrier: only the 32 CTAs of this row group produce our rows
        if (t > 0) {
            if (tid < 32) {
                const unsigned tgt = base + (unsigned)t;
                const unsigned* sl = &g_slot[rg * 32 + tid];
                while (ld_acq(sl) < tgt) __nanosleep(32);
            }
        }
        __syncthreads();

        // fill Hs with h[t-1] (L2-coherent reads; conflict-free STS, stride 33)
        const float* hp = (t == 0) ? h0 : (outputs + (size_t)(t - 1) * B_ * H_);
#pragma unroll
        for (int a = 0; a < 4; ++a) {
            const int rr = (tid >> 5) + a * 8;
            const float* src = hp + (size_t)(r0 + rr) * H_;
            float* dst = Hs + rr;
#pragma unroll
            for (int b = 0; b < 8; ++b) {
                const int k = (tid & 31) + b * 32;
                dst[k * 33] = __ldcg(src + k);
            }
        }
        __syncthreads();

        // GEMM: 4 rows x 4 cols per thread over K'=64 (packed f32x2)
        u64 acc2[4][2];
#pragma unroll
        for (int e = 0; e < 4; ++e) { acc2[e][0] = 0ULL; acc2[e][1] = 0ULL; }
        {
            const float* hq = Hs + wi2 * 4;
            const float* wq = Ws + wj2 * 4;
#pragma unroll 4
            for (int k = 0; k < 64; ++k) {
                const int kk = kbase + k;
                const float* hrow = hq + kk * 33;
                const float h0v = hrow[0], h1v = hrow[1], h2v = hrow[2], h3v = hrow[3];
                ulonglong2 w2 = *(const ulonglong2*)(wq + kk * 32);
                u64 hd;
                asm("mov.b64 %0, {%1, %1};" : "=l"(hd) : "f"(h0v));
                asm("fma.rn.f32x2 %0, %1, %2, %0;" : "+l"(acc2[0][0]) : "l"(hd), "l"(w2.x));
                asm("fma.rn.f32x2 %0, %1, %2, %0;" : "+l"(acc2[0][1]) : "l"(hd), "l"(w2.y));
                asm("mov.b64 %0, {%1, %1};" : "=l"(hd) : "f"(h1v));
                asm("fma.rn.f32x2 %0, %1, %2, %0;" : "+l"(acc2[1][0]) : "l"(hd), "l"(w2.x));
                asm("fma.rn.f32x2 %0, %1, %2, %0;" : "+l"(acc2[1][1]) : "l"(hd), "l"(w2.y));
                asm("mov.b64 %0, {%1, %1};" : "=l"(hd) : "f"(h2v));
                asm("fma.rn.f32x2 %0, %1, %2, %0;" : "+l"(acc2[2][0]) : "l"(hd), "l"(w2.x));
                asm("fma.rn.f32x2 %0, %1, %2, %0;" : "+l"(acc2[2][1]) : "l"(hd), "l"(w2.y));
                asm("mov.b64 %0, {%1, %1};" : "=l"(hd) : "f"(h3v));
                asm("fma.rn.f32x2 %0, %1, %2, %0;" : "+l"(acc2[3][0]) : "l"(hd), "l"(w2.x));
                asm("fma.rn.f32x2 %0, %1, %2, %0;" : "+l"(acc2[3][1]) : "l"(hd), "l"(w2.y));
            }
        }

        // store k-partials (gred is its own region -> no sync needed first)
#pragma unroll
        for (int e = 0; e < 4; ++e) {
            float2 p0, p1;
            asm("mov.b64 {%0, %1}, %2;" : "=f"(p0.x), "=f"(p0.y) : "l"(acc2[e][0]));
            asm("mov.b64 {%0, %1}, %2;" : "=f"(p1.x), "=f"(p1.y) : "l"(acc2[e][1]));
            *(float4*)(gred + (size_t)(kg * 32 + wi2 * 4 + e) * 36 + wj2 * 4) =
                make_float4(p0.x, p0.y, p1.x, p1.y);
        }
        __syncthreads();

        // reduce 4 k-partials, add preact, write gate exchange
        {
            float4 s = make_float4(0.f, 0.f, 0.f, 0.f);
#pragma unroll
            for (int q = 0; q < 4; ++q) {
                float4 v = *(const float4*)(gred + (size_t)(q * 32 + r) * 36 + oc0);
                s.x += v.x; s.y += v.y; s.z += v.z; s.w += v.w;
            }
            gsm[r * 33 + oc0 + 0] = s.x + pv.x;
            gsm[r * 33 + oc0 + 1] = s.y + pv.y;
            gsm[r * 33 + oc0 + 2] = s.z + pv.z;
            gsm[r * 33 + oc0 + 3] = s.w + pv.w;
        }
        __syncthreads();

        // fused cell update
        {
            const float iv = gsm[r * 33 +  0 + c2];
            const float fv = gsm[r * 33 +  8 + c2];
            const float ov = gsm[r * 33 + 16 + c2];
            const float gv = gsm[r * 33 + 24 + c2];
            const float ig = 1.f / (1.f + expf(-iv));
            const float fg = 1.f / (1.f + expf(-fv));
            const float og = 1.f / (1.f + expf(-ov));
            const float gt = tanhf(gv);
            creg = fg * creg + ig * gt;
            const float hn = og * tanhf(creg);
            const int row = r0 + r, col = hc0 + c2;
            outputs[(size_t)t * B_ * H_ + row * H_ + col] = hn;
            if (t == T_ - 1) {
                hfin[row * H_ + col] = hn;
                cfin[row * H_ + col] = creg;
            }
        }

        // publish step t
        __threadfence();
        __syncthreads();
        if (tid == 0) st_rel(&g_slot[bid], base + (unsigned)(t + 1));
    }
}

extern "C" void kernel_launch(void* const* d_in, const int* in_sizes, int n_in,
                              void* d_out, int out_size)
{
    (void)in_sizes; (void)n_in; (void)out_size;
    const float* x   = (const float*)d_in[0];
    const float* h0  = (const float*)d_in[1];
    const float* c0  = (const float*)d_in[2];
    const float* Wi  = (const float*)d_in[3];
    const float* bi  = (const float*)d_in[4];
    const float* Wh  = (const float*)d_in[5];
    const float* bh  = (const float*)d_in[6];

    float* out     = (float*)d_out;
    float* outputs = out;
    float* hfin    = out + (size_t)T_ * B_ * H_;
    float* cfin    = hfin + (size_t)B_ * H_;

    float* pre;
    cudaGetSymbolAddress((void**)&pre, g_preact);

    // Hs 33792 + Ws 32768 + gred 18432 + gsm 4224 = 89216 B
    const int smem_bytes = (256 * 33 + 256 * 32 + 4 * 32 * 36 + 32 * 33) *
                           (int)sizeof(float);
    cudaFuncSetAttribute(lstm_scan, cudaFuncAttributeMaxDynamicSharedMemorySize,
                         smem_bytes);

    dim3 g1(8, T_);
    lstm_phase1<<<g1, 256>>>(x, Wi, bi, bh, pre);

    lstm_scan<<<NCTA, 256, smem_bytes>>>(h0, c0, Wh, pre, outputs, hfin, cfin);
}